// round 7
// baseline (speedup 1.0000x reference)
#include <cuda_runtime.h>
#include <math.h>

#define NN 2048
#define MM 32
#define GA 128                   // grid: <=148 -> all co-resident in wave 1, spin-safe
#define TB 512                   // threads per block (16 warps)
#define NWB 16                   // warps per block
#define RPB (NN / GA)            // 16 rows per block (1 row per warp)

// ---- scratch (no device allocations allowed) ----
__device__ float g_pmom[GA][10][MM];   // per-block raw weighted moments
__device__ float g_pmax[GA][MM];       // per-block per-column max(diff)
__device__ float g_bco[11][MM];        // b_0..b_9, row 10 = W  (built by block 0)
__device__ float g_f[MM];              // per-column normalization factor
__device__ float g_part[GA];           // per-block partial loss
__device__ volatile int g_bar;         // barrier counter (polled by block 0 only)
__device__ volatile int g_flag;        // coefficients-ready broadcast flag
__device__ int   g_cnt;                // final-election counter

// A[m][p] = C[(m+p)/2] * binom(m+p, m) * (-1)^p for (m+p) odd <= 9, else 0.
// b_m = sum_p A[m][p] * Mn_p, Mn_p = M'_p * f^p.  (precomputed in fp64 on host)
__device__ __constant__ float d_A[10][10] = {
  {0.f,-0.5641895835477563f,0.f, 0.18806319451591878f,0.f,-0.05641895835477563f,0.f, 0.013433085322565627f,0.f,-0.0026119888127211866f},
  {0.5641895835477563f,0.f,-0.5641895835477563f,0.f, 0.28209479177387815f,0.f,-0.09403159725795939f,0.f, 0.023507899314490679f,0.f},
  {0.f, 0.5641895835477563f,0.f,-0.5641895835477563f,0.f, 0.28209479177387817f,0.f,-0.09403159725796272f,0.f,0.f},
  {-0.18806319451591878f,0.f, 0.5641895835477563f,0.f,-0.47015798628979696f,0.f, 0.21940705866857968f,0.f,0.f,0.f},
  {0.f,-0.28209479177387815f,0.f, 0.47015798628979696f,0.f,-0.32911059040286952f,0.f,0.f,0.f,0.f},
  {0.05641895835477563f,0.f,-0.28209479177387817f,0.f, 0.32911059040286952f,0.f,0.f,0.f,0.f,0.f},
  {0.f, 0.09403159725795939f,0.f,-0.21940705866857968f,0.f,0.f,0.f,0.f,0.f,0.f},
  {-0.013433085322565627f,0.f, 0.09403159725796272f,0.f,0.f,0.f,0.f,0.f,0.f,0.f},
  {0.f,-0.023507899314490679f,0.f,0.f,0.f,0.f,0.f,0.f,0.f,0.f},
  {0.0026119888127211866f,0.f,0.f,0.f,0.f,0.f,0.f,0.f,0.f,0.f}
};

__global__ void __launch_bounds__(TB, 1) fused(const float* __restrict__ risk,
                                               const float* __restrict__ expr,
                                               const float* __restrict__ tr,
                                               const float* __restrict__ ev,
                                               const float* __restrict__ sigma,
                                               float* __restrict__ out) {
    const int tid  = threadIdx.x;
    const int warp = tid >> 5, lane = tid & 31;

    __shared__ float smom[NWB][10][MM];   // 20 KB
    __shared__ float smax[NWB][MM];       // 2 KB
    __shared__ float sM[10][MM];
    __shared__ float sf[MM];
    __shared__ float wred[NWB];
    __shared__ int   sflag;

    const float sigv = sigma[0];

    // ---------------- Phase 1: one element per thread ----------------
    const int idx = (blockIdx.x * RPB + warp) * MM + lane;
    const float rv  = risk[idx];
    const float d   = expr[idx] - tr[idx];
    const float evv = ev[idx];
    const float T   = __expf(d);
    const float w   = __expf(rv);

    {
        float m[10];
        float p = w;
        m[0] = p;
#pragma unroll
        for (int q = 1; q < 10; ++q) { p *= T; m[q] = p; }
        smax[warp][lane] = d;
#pragma unroll
        for (int q = 0; q < 10; ++q) smom[warp][q][lane] = m[q];
    }
    __syncthreads();

    if (warp == 0) {
        float v = smax[0][lane];
#pragma unroll
        for (int i = 1; i < NWB; ++i) v = fmaxf(v, smax[i][lane]);
        g_pmax[blockIdx.x][lane] = v;
    }
    if (tid < 320) {
        const int q = tid >> 5, kk = tid & 31;
        float s = smom[0][q][kk];
#pragma unroll
        for (int i = 1; i < NWB; ++i) s += smom[i][q][kk];
        g_pmom[blockIdx.x][q][kk] = s;
    }

    // ---------------- Arrive at barrier ----------------
    __threadfence();
    __syncthreads();
    if (tid == 0) {
        sflag = 0;
        atomicAdd((int*)&g_bar, 1);
    }
    __syncthreads();

    if (blockIdx.x == 0) {
        // -------- Block 0: wait for all partials, build coefficients --------
        if (tid == 0) {
            while (g_bar < GA) { __nanosleep(32); }
            __threadfence();
        }
        __syncthreads();

        if (tid < MM) {               // column max -> f (coalesced per iteration)
            float v = g_pmax[0][tid];
#pragma unroll 4
            for (int b = 1; b < GA; ++b) v = fmaxf(v, g_pmax[b][tid]);
            float scale = 1.0f / (2.0f * sigv * sqrtf(2.0f));
            float f = scale * __expf(-v);
            sf[tid] = f;
            g_f[tid] = f;
        }
        __syncthreads();
        if (tid < 320) {              // moment reduce (coalesced), normalize
            const int q = tid >> 5, kk = tid & 31;
            float s0 = 0.f, s1 = 0.f, s2 = 0.f, s3 = 0.f;
#pragma unroll
            for (int b = 0; b < GA; b += 4) {
                s0 += g_pmom[b + 0][q][kk];
                s1 += g_pmom[b + 1][q][kk];
                s2 += g_pmom[b + 2][q][kk];
                s3 += g_pmom[b + 3][q][kk];
            }
            float s = (s0 + s1) + (s2 + s3);
            float f = sf[kk], fp = 1.0f;
#pragma unroll
            for (int i = 0; i < 9; ++i) if (i < q) fp *= f;
            sM[q][kk] = s * fp;
        }
        __syncthreads();
        if (tid < 320) {              // b_m = sum_p A[m][p] * Mn_p
            const int md = tid >> 5, kk = tid & 31;
            float bm = 0.0f;
#pragma unroll
            for (int p = 0; p < 10; ++p) bm = fmaf(d_A[md][p], sM[p][kk], bm);
            g_bco[md][kk] = bm;
            if (md == 0) g_bco[10][kk] = sM[0][kk];   // W
        }
        __threadfence();
        __syncthreads();
        if (tid == 0) g_flag = 1;     // broadcast: coefficients ready
    } else {
        // -------- Other blocks: wait for the coefficients flag --------
        if (tid == 0) {
            while (g_flag == 0) { __nanosleep(32); }
            __threadfence();
        }
        __syncthreads();
    }

    // ---------------- Phase 3: eval (T, w, rv, evv still in registers) ----------
    float bb[10];
#pragma unroll
    for (int q = 0; q < 10; ++q) bb[q] = g_bco[q][lane];
    const float W = g_bco[10][lane];
    const float f = g_f[lane];

    float x = T * f;
    float s = bb[9];
#pragma unroll
    for (int q = 8; q >= 0; --q) s = fmaf(s, x, bb[q]);
    float cum = fmaf(0.5f, W + w, -s);
    float acc = (rv - __logf(cum)) * evv;

#pragma unroll
    for (int o = 16; o > 0; o >>= 1) acc += __shfl_down_sync(0xffffffffu, acc, o);
    if (lane == 0) wred[warp] = acc;
    __syncthreads();
    if (tid == 0) {
        float b = 0.0f;
#pragma unroll
        for (int i = 0; i < NWB; ++i) b += wred[i];
        g_part[blockIdx.x] = b;
        __threadfence();
        sflag = (atomicAdd(&g_cnt, 1) == GA - 1);
    }
    __syncthreads();
    if (!sflag) return;

    // ---------------- Elected last block: final reduce + reset --------
    __threadfence();
    if (warp == 0) {
        float v = 0.0f;
#pragma unroll
        for (int i = 0; i < GA / 32; ++i) v += g_part[lane + i * 32];
#pragma unroll
        for (int o = 16; o > 0; o >>= 1) v += __shfl_down_sync(0xffffffffu, v, o);
        if (lane == 0) {
            out[0] = -v;
            g_cnt  = 0;        // safe: all blocks already passed all counters
            g_bar  = 0;
            g_flag = 0;
        }
    }
}

extern "C" void kernel_launch(void* const* d_in, const int* in_sizes, int n_in,
                              void* d_out, int out_size) {
    const float* risk  = (const float*)d_in[0];
    const float* expr  = (const float*)d_in[1];
    const float* tr    = (const float*)d_in[2];
    const float* ev    = (const float*)d_in[3];
    const float* sigma = (const float*)d_in[4];
    float* out = (float*)d_out;

    fused<<<GA, TB>>>(risk, expr, tr, ev, sigma, out);
}

// round 8
// speedup vs baseline: 1.7180x; 1.7180x over previous
#include <cuda_runtime.h>
#include <math.h>

#define NN 2048
#define MM 32
#define GA 64                    // grid: 64 <= 148 SMs -> all co-resident, spin barrier safe
#define TB 1024                  // threads per block (32 warps)
#define NWB 32                   // warps per block
#define NMOM 8                   // moments M_0..M_7 (degree-7 erf series)

// ---- scratch (no device allocations allowed) ----
__device__ float g_pmom[GA][NMOM][MM]; // per-block raw weighted moments
__device__ float g_pmax[GA][MM];       // per-block per-column max(diff)
__device__ float g_part[GA];           // per-block partial loss
__device__ volatile int g_bar;         // grid barrier counter
__device__ int   g_cnt;                // final-election counter

// A[m][p] = C[(m+p-1)/2] * binom(m+p, m) * (-1)^p for (m+p) odd <= 7, else 0.
// 0.5*erf(d) ~ C0 d + C1 d^3 + C2 d^5 + C3 d^7 (|d|<=0.3536, trunc err ~5e-7 rel)
__device__ __constant__ float d_A[NMOM][NMOM] = {
  {0.f,-0.5641895835477563f,0.f, 0.18806319451591878f,0.f,-0.05641895835477563f,0.f, 0.013433085322565627f},
  {0.5641895835477563f,0.f,-0.5641895835477563f,0.f, 0.28209479177387815f,0.f,-0.09403159725795939f,0.f},
  {0.f, 0.5641895835477563f,0.f,-0.5641895835477563f,0.f, 0.28209479177387817f,0.f,0.f},
  {-0.18806319451591878f,0.f, 0.5641895835477563f,0.f,-0.47015798628979696f,0.f,0.f,0.f},
  {0.f,-0.28209479177387815f,0.f, 0.47015798628979696f,0.f,0.f,0.f,0.f},
  {0.05641895835477563f,0.f,-0.28209479177387817f,0.f,0.f,0.f,0.f,0.f},
  {0.f, 0.09403159725795939f,0.f,0.f,0.f,0.f,0.f,0.f},
  {-0.013433085322565627f,0.f,0.f,0.f,0.f,0.f,0.f,0.f}
};

__global__ void __launch_bounds__(TB, 1) fused(const float* __restrict__ risk,
                                               const float* __restrict__ expr,
                                               const float* __restrict__ tr,
                                               const float* __restrict__ ev,
                                               const float* __restrict__ sigma,
                                               float* __restrict__ out) {
    const int tid  = threadIdx.x;
    const int warp = tid >> 5, lane = tid & 31;

    __shared__ float smom[NWB][NMOM][MM];   // 32 KB
    __shared__ float smax[NWB][MM];         // 4 KB
    __shared__ float sred[4][NMOM][MM];     // 4 KB: phase-2 split partials
    __shared__ float sM[NMOM][MM];          // normalized moments
    __shared__ float sbb[NMOM + 1][MM];     // b_0..b_7, row NMOM = W
    __shared__ float sf[MM];
    __shared__ float wred[NWB];
    __shared__ int   sflag;

    const float sigv = sigma[0];

    // ---------------- Phase 1: one element per thread ----------------
    const int idx = (blockIdx.x * NWB + warp) * MM + lane;
    const float rv  = risk[idx];
    const float d   = expr[idx] - tr[idx];
    const float evv = ev[idx];
    const float T   = __expf(d);
    const float w   = __expf(rv);

    {
        float p = w;
        smom[warp][0][lane] = p;
#pragma unroll
        for (int q = 1; q < NMOM; ++q) { p *= T; smom[warp][q][lane] = p; }
        smax[warp][lane] = d;
    }
    __syncthreads();

    if (warp == 0) {                       // block max per column
        float v = smax[0][lane];
#pragma unroll
        for (int i = 1; i < NWB; ++i) v = fmaxf(v, smax[i][lane]);
        g_pmax[blockIdx.x][lane] = v;
    }
    if (tid < NMOM * MM) {                 // block moment sums (256 threads)
        const int q = tid >> 5, kk = tid & 31;
        float s0 = 0.f, s1 = 0.f, s2 = 0.f, s3 = 0.f;
#pragma unroll
        for (int i = 0; i < NWB; i += 4) {
            s0 += smom[i + 0][q][kk];
            s1 += smom[i + 1][q][kk];
            s2 += smom[i + 2][q][kk];
            s3 += smom[i + 3][q][kk];
        }
        g_pmom[blockIdx.x][q][kk] = (s0 + s1) + (s2 + s3);
    }

    // ---------------- Grid barrier (all blocks spin; proven R6 pattern) ----------
    __threadfence();
    __syncthreads();
    if (tid == 0) {
        sflag = 0;
        atomicAdd((int*)&g_bar, 1);
        while (g_bar < GA) { __nanosleep(32); }
        __threadfence();
    }
    __syncthreads();

    // ---------------- Phase 2: redundant fp32 coefficient build (per block) ------
    // column max over 64 blocks: 256 threads, 8 strided loads each (MLP 8)
    if (tid < 8 * MM) {
        const int i = tid >> 5, kk = lane;
        float v = -1e30f;
#pragma unroll
        for (int j = 0; j < GA / 8; ++j) v = fmaxf(v, g_pmax[i + j * 8][kk]);
        smax[i][kk] = v;
    }
    __syncthreads();
    if (tid < MM) {
        float v = smax[0][tid];
#pragma unroll
        for (int i = 1; i < 8; ++i) v = fmaxf(v, smax[i][tid]);
        float scale = 1.0f / (2.0f * sigv * sqrtf(2.0f));
        sf[tid] = scale * __expf(-v);
    }
    // moment reduce, 4-way split: 1024 threads each sum 16 of 64 blocks (MLP via unroll)
    {
        const int j = tid >> 8;                  // 0..3
        const int o = tid & 255;                 // (q,k)
        const int q = o >> 5, kk = o & 31;
        float s0 = 0.f, s1 = 0.f, s2 = 0.f, s3 = 0.f;
#pragma unroll
        for (int b = 0; b < GA / 4; b += 4) {    // 16 loads, 4 accumulators
            s0 += g_pmom[j * (GA / 4) + b + 0][q][kk];
            s1 += g_pmom[j * (GA / 4) + b + 1][q][kk];
            s2 += g_pmom[j * (GA / 4) + b + 2][q][kk];
            s3 += g_pmom[j * (GA / 4) + b + 3][q][kk];
        }
        sred[j][q][kk] = (s0 + s1) + (s2 + s3);
    }
    __syncthreads();
    if (tid < NMOM * MM) {                       // combine 4, normalize by f^q
        const int q = tid >> 5, kk = tid & 31;
        float s = (sred[0][q][kk] + sred[1][q][kk]) + (sred[2][q][kk] + sred[3][q][kk]);
        float f = sf[kk], fp = 1.0f;
#pragma unroll
        for (int i = 0; i < NMOM - 1; ++i) if (i < q) fp *= f;
        sM[q][kk] = s * fp;
    }
    __syncthreads();
    if (tid < NMOM * MM) {                       // b_m = sum_p A[m][p] * Mn_p
        const int md = tid >> 5, kk = tid & 31;
        float bm = 0.0f;
#pragma unroll
        for (int p = 0; p < NMOM; ++p) bm = fmaf(d_A[md][p], sM[p][kk], bm);
        sbb[md][kk] = bm;
        if (md == 0) sbb[NMOM][kk] = sM[0][kk];  // W
    }
    __syncthreads();

    // ---------------- Phase 3: eval (rv, T, w, evv still in registers) ----------
    float bb[NMOM];
#pragma unroll
    for (int q = 0; q < NMOM; ++q) bb[q] = sbb[q][lane];
    const float W = sbb[NMOM][lane];
    const float f = sf[lane];

    float x = T * f;
    float s = bb[NMOM - 1];
#pragma unroll
    for (int q = NMOM - 2; q >= 0; --q) s = fmaf(s, x, bb[q]);
    float cum = fmaf(0.5f, W + w, -s);
    float acc = (rv - __logf(cum)) * evv;

#pragma unroll
    for (int o = 16; o > 0; o >>= 1) acc += __shfl_down_sync(0xffffffffu, acc, o);
    if (lane == 0) wred[warp] = acc;
    __syncthreads();
    if (tid == 0) {
        float b0 = 0.f, b1 = 0.f, b2 = 0.f, b3 = 0.f;
#pragma unroll
        for (int i = 0; i < NWB; i += 4) {
            b0 += wred[i]; b1 += wred[i + 1]; b2 += wred[i + 2]; b3 += wred[i + 3];
        }
        g_part[blockIdx.x] = (b0 + b1) + (b2 + b3);
        __threadfence();
        sflag = (atomicAdd(&g_cnt, 1) == GA - 1);
    }
    __syncthreads();
    if (!sflag) return;

    // ---------------- Elected last block: final reduce + counter reset ----------
    __threadfence();
    if (warp == 0) {
        float v = g_part[lane] + g_part[lane + 32];   // GA == 64
#pragma unroll
        for (int o = 16; o > 0; o >>= 1) v += __shfl_down_sync(0xffffffffu, v, o);
        if (lane == 0) {
            out[0] = -v;
            g_cnt = 0;         // safe: every block already passed both counters
            g_bar = 0;
        }
    }
}

extern "C" void kernel_launch(void* const* d_in, const int* in_sizes, int n_in,
                              void* d_out, int out_size) {
    const float* risk  = (const float*)d_in[0];
    const float* expr  = (const float*)d_in[1];
    const float* tr    = (const float*)d_in[2];
    const float* ev    = (const float*)d_in[3];
    const float* sigma = (const float*)d_in[4];
    float* out = (float*)d_out;

    fused<<<GA, TB>>>(risk, expr, tr, ev, sigma, out);
}

// round 9
// speedup vs baseline: 1.7642x; 1.0269x over previous
#include <cuda_runtime.h>
#include <math.h>

#define NN 2048
#define MM 32
#define NMOM 8                 // moments M_0..M_7 (degree-7 erf series)
#define GAA 64                 // kA grid
#define TBA 512                // kA threads (16 warps), 2 elements/thread
#define NWA 16
#define GBB 128                // kB grid
#define TBB 512                // kB threads (16 warps), 1 element/thread
#define NWBB 16

// ---- scratch (no device allocations allowed) ----
__device__ float g_pmom[GAA][NMOM][MM]; // per-block raw weighted moments
__device__ float g_pmax[GAA][MM];       // per-block per-column max(diff)
__device__ float g_part[GBB];           // kB per-block partial loss
__device__ int   g_cnt;                 // kB final-election counter

// A[m][p] = C[(m+p-1)/2] * binom(m+p, m) * (-1)^p for (m+p) odd <= 7, else 0.
// 0.5*erf(d) ~ C0 d + C1 d^3 + C2 d^5 + C3 d^7  (|d| <= 0.3536, trunc ~5e-7 rel)
__device__ __constant__ float d_A[NMOM][NMOM] = {
  {0.f,-0.5641895835477563f,0.f, 0.18806319451591878f,0.f,-0.05641895835477563f,0.f, 0.013433085322565627f},
  {0.5641895835477563f,0.f,-0.5641895835477563f,0.f, 0.28209479177387815f,0.f,-0.09403159725795939f,0.f},
  {0.f, 0.5641895835477563f,0.f,-0.5641895835477563f,0.f, 0.28209479177387817f,0.f,0.f},
  {-0.18806319451591878f,0.f, 0.5641895835477563f,0.f,-0.47015798628979696f,0.f,0.f,0.f},
  {0.f,-0.28209479177387815f,0.f, 0.47015798628979696f,0.f,0.f,0.f,0.f},
  {0.05641895835477563f,0.f,-0.28209479177387817f,0.f,0.f,0.f,0.f,0.f},
  {0.f, 0.09403159725795939f,0.f,0.f,0.f,0.f,0.f,0.f},
  {-0.013433085322565627f,0.f,0.f,0.f,0.f,0.f,0.f,0.f}
};

// ---------------------------------------------------------------------------
// kA: raw weighted moments + per-column max partials. 2 elements per thread.
// lane = column (both elements), coalesced loads. Kernel boundary = barrier.
// ---------------------------------------------------------------------------
__global__ void __launch_bounds__(TBA, 1) kA(const float* __restrict__ risk,
                                             const float* __restrict__ expr,
                                             const float* __restrict__ tr) {
    const int tid  = threadIdx.x;
    const int warp = tid >> 5, lane = tid & 31;

    __shared__ float smom[NWA][NMOM][MM];   // 16 KB
    __shared__ float smax[NWA][MM];         // 2 KB

    const int i0 = blockIdx.x * (2 * TBA) + tid;   // element 0
    const int i1 = i0 + TBA;                       // element 1 (same lane/column)

    const float d0 = expr[i0] - tr[i0];
    const float d1 = expr[i1] - tr[i1];
    const float T0 = __expf(d0),       T1 = __expf(d1);
    float       p0 = __expf(risk[i0]), p1 = __expf(risk[i1]);

    smax[warp][lane] = fmaxf(d0, d1);
    smom[warp][0][lane] = p0 + p1;
#pragma unroll
    for (int q = 1; q < NMOM; ++q) {
        p0 *= T0; p1 *= T1;
        smom[warp][q][lane] = p0 + p1;
    }
    __syncthreads();

    if (tid < 32) {                        // column max over 16 warps
        float v = smax[0][tid];
#pragma unroll
        for (int i = 1; i < NWA; ++i) v = fmaxf(v, smax[i][tid]);
        g_pmax[blockIdx.x][tid] = v;
    }
    if (tid < NMOM * MM) {                 // moment sums over 16 warps (4-acc)
        const int q = tid >> 5, kk = tid & 31;
        float s0 = 0.f, s1 = 0.f, s2 = 0.f, s3 = 0.f;
#pragma unroll
        for (int i = 0; i < NWA; i += 4) {
            s0 += smom[i + 0][q][kk];
            s1 += smom[i + 1][q][kk];
            s2 += smom[i + 2][q][kk];
            s3 += smom[i + 3][q][kk];
        }
        g_pmom[blockIdx.x][q][kk] = (s0 + s1) + (s2 + s3);
    }
}

// ---------------------------------------------------------------------------
// kB: prefetch element + exp, redundant fp32 coefficient build, eval, reduce,
//     single election for the final sum. 1 element per thread.
// ---------------------------------------------------------------------------
__global__ void __launch_bounds__(TBB, 1) kB(const float* __restrict__ risk,
                                             const float* __restrict__ expr,
                                             const float* __restrict__ tr,
                                             const float* __restrict__ ev,
                                             const float* __restrict__ sigma,
                                             float* __restrict__ out) {
    const int tid  = threadIdx.x;
    const int warp = tid >> 5, lane = tid & 31;

    __shared__ float sred[2][NMOM][MM];     // moment reduce halves
    __shared__ float smax[8][MM];           // max reduce partials
    __shared__ float sM[NMOM][MM];          // normalized moments
    __shared__ float sbb[NMOM + 1][MM];     // b_0..b_7, row NMOM = W
    __shared__ float sf[MM];
    __shared__ float wred[NWBB];
    __shared__ int   sflag;

    // ---- prefetch this thread's element; exps overlap with phase 2 ----
    const int idx   = blockIdx.x * TBB + tid;      // lane = column
    const float rv  = risk[idx];
    const float dd  = expr[idx] - tr[idx];
    const float evv = ev[idx];
    const float sigv = sigma[0];
    const float T   = __expf(dd);
    const float w   = __expf(rv);

    // ---- phase 2a: moment partial reduce (512 thr, 2 halves) + max partials ----
    {
        const int j = tid >> 8;                    // 0..1
        const int o = tid & 255;
        const int q = o >> 5, kk = o & 31;
        float s0 = 0.f, s1 = 0.f, s2 = 0.f, s3 = 0.f;
#pragma unroll
        for (int b = 0; b < GAA / 2; b += 4) {     // 32 loads, 4 accumulators
            s0 += g_pmom[j * (GAA / 2) + b + 0][q][kk];
            s1 += g_pmom[j * (GAA / 2) + b + 1][q][kk];
            s2 += g_pmom[j * (GAA / 2) + b + 2][q][kk];
            s3 += g_pmom[j * (GAA / 2) + b + 3][q][kk];
        }
        sred[j][q][kk] = (s0 + s1) + (s2 + s3);
    }
    if (tid < 8 * MM) {                            // max partials (8 strided each)
        const int i = tid >> 5;
        float v = -1e30f;
#pragma unroll
        for (int jj = 0; jj < GAA / 8; ++jj) v = fmaxf(v, g_pmax[i + jj * 8][lane]);
        smax[i][lane] = v;
    }
    __syncthreads();

    // ---- phase 2b: f, then normalized moments ----
    float sraw = 0.0f;
    if (tid < NMOM * MM) {
        const int q = tid >> 5, kk = tid & 31;
        sraw = sred[0][q][kk] + sred[1][q][kk];
    }
    if (tid < 32) {
        float v = smax[0][tid];
#pragma unroll
        for (int i = 1; i < 8; ++i) v = fmaxf(v, smax[i][tid]);
        float scale = 1.0f / (2.0f * sigv * sqrtf(2.0f));
        sf[tid] = scale * __expf(-v);
    }
    __syncthreads();
    if (tid < NMOM * MM) {
        const int q = tid >> 5, kk = tid & 31;
        float f = sf[kk], fp = 1.0f;
#pragma unroll
        for (int i = 0; i < NMOM - 1; ++i) if (i < q) fp *= f;
        sM[q][kk] = sraw * fp;                     // Mn_q = M'_q * f^q
    }
    __syncthreads();
    if (tid < NMOM * MM) {                         // b_m = sum_p A[m][p] * Mn_p
        const int md = tid >> 5, kk = tid & 31;
        float bm = 0.0f;
#pragma unroll
        for (int p = 0; p < NMOM; ++p) bm = fmaf(d_A[md][p], sM[p][kk], bm);
        sbb[md][kk] = bm;
        if (md == 0) sbb[NMOM][kk] = sM[0][kk];    // W
    }
    __syncthreads();

    // ---- phase 3: eval (element data already in registers) ----
    float bb[NMOM];
#pragma unroll
    for (int q = 0; q < NMOM; ++q) bb[q] = sbb[q][lane];
    const float W = sbb[NMOM][lane];
    const float f = sf[lane];

    float x = T * f;
    float s = bb[NMOM - 1];
#pragma unroll
    for (int q = NMOM - 2; q >= 0; --q) s = fmaf(s, x, bb[q]);
    float cum = fmaf(0.5f, W + w, -s);
    float acc = (rv - __logf(cum)) * evv;

#pragma unroll
    for (int o = 16; o > 0; o >>= 1) acc += __shfl_down_sync(0xffffffffu, acc, o);
    if (lane == 0) wred[warp] = acc;
    __syncthreads();
    if (tid == 0) {
        float b0 = 0.f, b1 = 0.f, b2 = 0.f, b3 = 0.f;
#pragma unroll
        for (int i = 0; i < NWBB; i += 4) {
            b0 += wred[i]; b1 += wred[i + 1]; b2 += wred[i + 2]; b3 += wred[i + 3];
        }
        g_part[blockIdx.x] = (b0 + b1) + (b2 + b3);
        __threadfence();
        sflag = (atomicAdd(&g_cnt, 1) == GBB - 1);
    }
    __syncthreads();
    if (!sflag) return;

    // ---- elected last block: final reduce + counter reset ----
    __threadfence();
    if (warp == 0) {
        float v = 0.0f;
#pragma unroll
        for (int i = 0; i < GBB / 32; ++i) v += g_part[lane + i * 32];
#pragma unroll
        for (int o = 16; o > 0; o >>= 1) v += __shfl_down_sync(0xffffffffu, v, o);
        if (lane == 0) {
            out[0] = -v;
            g_cnt = 0;           // safe: all blocks already passed the counter
        }
    }
}

extern "C" void kernel_launch(void* const* d_in, const int* in_sizes, int n_in,
                              void* d_out, int out_size) {
    const float* risk  = (const float*)d_in[0];
    const float* expr  = (const float*)d_in[1];
    const float* tr    = (const float*)d_in[2];
    const float* ev    = (const float*)d_in[3];
    const float* sigma = (const float*)d_in[4];
    float* out = (float*)d_out;

    kA<<<GAA, TBA>>>(risk, expr, tr);
    kB<<<GBB, TBB>>>(risk, expr, tr, ev, sigma, out);
}